// round 2
// baseline (speedup 1.0000x reference)
#include <cuda_runtime.h>

// Problem constants
#define B_   8
#define OBJ_ 128
#define INP_ 64
#define HID_ 256
#define D_   192          // 3*INP
#define ROWS_ (B_*OBJ_)   // 1024

// Scratch (allocation-free rule: __device__ globals)
__device__ float g_ea[ROWS_ * HID_];
__device__ float g_eb[ROWS_ * HID_];
__device__ float g_pooled[ROWS_ * HID_];

// ---------------------------------------------------------------------------
// Encoder: ea[row,h] = sum_d x[row,d] * w_enc[d,h];  eb uses w_enc[D+d,h]
// x = concat(x0,x1,x2) along last dim (64 each)
// ---------------------------------------------------------------------------
__global__ void enc_kernel(const float* __restrict__ x0,
                           const float* __restrict__ x1,
                           const float* __restrict__ x2,
                           const float* __restrict__ w_enc) {
    __shared__ float xs[D_];
    const int row = blockIdx.x;        // b*OBJ + n
    const int tid = threadIdx.x;       // 0..255
    if (tid < D_) {
        int part = tid >> 6;           // /64
        int d    = tid & 63;
        const float* src = (part == 0) ? x0 : ((part == 1) ? x1 : x2);
        xs[tid] = src[row * INP_ + d];
    }
    __syncthreads();
    float s1 = 0.f, s2 = 0.f;
    #pragma unroll 8
    for (int d = 0; d < D_; d++) {
        float xv = xs[d];
        s1 = fmaf(xv, w_enc[d * HID_ + tid], s1);
        s2 = fmaf(xv, w_enc[(D_ + d) * HID_ + tid], s2);
    }
    g_ea[row * HID_ + tid] = s1;
    g_eb[row * HID_ + tid] = s2;
}

// ---------------------------------------------------------------------------
// Main pairwise MLP + mean pooling.
// One CTA per (b,i). j in 2 chunks of 64. 3 layers of 256x256 GEMM in smem.
// Block = (32,8) = 256 threads. Thread tile = 8 rows x 8 cols.
// ---------------------------------------------------------------------------
#define JC 64
#define KC 32
// smem floats: 2*JC*HID (bufs) + KC*HID (W panel) + HID (ea) + HID (pooled)
#define SMEM_FLOATS (2*JC*HID_ + KC*HID_ + HID_ + HID_)
#define SMEM_BYTES  (SMEM_FLOATS * 4)

__global__ void __launch_bounds__(256, 1)
main_kernel(const float* __restrict__ b_enc,
            const float* __restrict__ w1, const float* __restrict__ b1,
            const float* __restrict__ w2, const float* __restrict__ b2,
            const float* __restrict__ w3, const float* __restrict__ b3) {
    extern __shared__ float sm[];
    float* buf0   = sm;                    // JC*HID
    float* buf1   = buf0 + JC * HID_;      // JC*HID
    float* wb     = buf1 + JC * HID_;      // KC*HID
    float* ea_s   = wb + KC * HID_;        // HID
    float* pooled = ea_s + HID_;           // HID

    const int bi = blockIdx.x;             // b*OBJ + i
    const int b  = bi >> 7;
    const int tx = threadIdx.x;            // 0..31 (col groups of 8)
    const int ty = threadIdx.y;            // 0..7  (row groups of 8)
    const int tid = ty * 32 + tx;

    ea_s[tid]   = g_ea[bi * HID_ + tid];
    pooled[tid] = 0.f;
    __syncthreads();

    const float* Ws[3] = {w1, w2, w3};
    const float* Bs[3] = {b1, b2, b3};

    for (int chunk = 0; chunk < 2; chunk++) {
        const int j0 = chunk * JC;
        // ---- build H0 = relu(ea + eb_j + b_enc) into buf0 ----
        const float* ebp = g_eb + (b * OBJ_ + j0) * HID_;
        #pragma unroll 4
        for (int idx = tid; idx < JC * HID_; idx += 256) {
            int h = idx & (HID_ - 1);
            float v = ea_s[h] + ebp[idx] + b_enc[h];
            buf0[idx] = fmaxf(v, 0.f);
        }
        __syncthreads();

        float* bin  = buf0;
        float* bout = buf1;
        #pragma unroll
        for (int L = 0; L < 3; L++) {
            const float* W    = Ws[L];
            const float* bias = Bs[L];
            float acc[8][8];
            #pragma unroll
            for (int r = 0; r < 8; r++)
                #pragma unroll
                for (int c = 0; c < 8; c++) acc[r][c] = 0.f;

            for (int k0 = 0; k0 < HID_; k0 += KC) {
                // stage W[k0..k0+KC) x HID into wb (KC*HID floats)
                const float4* Wg  = reinterpret_cast<const float4*>(W + k0 * HID_);
                float4*       wb4 = reinterpret_cast<float4*>(wb);
                #pragma unroll
                for (int t = 0; t < (KC * HID_ / 4) / 256; t++)
                    wb4[tid + t * 256] = Wg[tid + t * 256];
                __syncthreads();

                #pragma unroll 8
                for (int k = 0; k < KC; k++) {
                    float a[8];
                    #pragma unroll
                    for (int r = 0; r < 8; r++)
                        a[r] = bin[(ty * 8 + r) * HID_ + k0 + k];
                    const float4* wrow =
                        reinterpret_cast<const float4*>(wb + k * HID_ + tx * 8);
                    float4 wv0 = wrow[0];
                    float4 wv1 = wrow[1];
                    float wv[8] = {wv0.x, wv0.y, wv0.z, wv0.w,
                                   wv1.x, wv1.y, wv1.z, wv1.w};
                    #pragma unroll
                    for (int r = 0; r < 8; r++)
                        #pragma unroll
                        for (int c = 0; c < 8; c++)
                            acc[r][c] = fmaf(a[r], wv[c], acc[r][c]);
                }
                __syncthreads();
            }

            if (L < 2) {
                #pragma unroll
                for (int r = 0; r < 8; r++) {
                    #pragma unroll
                    for (int c = 0; c < 8; c++) {
                        float v = acc[r][c] + bias[tx * 8 + c];
                        bout[(ty * 8 + r) * HID_ + tx * 8 + c] = fmaxf(v, 0.f);
                    }
                }
                __syncthreads();
                float* t = bin; bin = bout; bout = t;
            } else {
                // layer 3: no relu; reduce rows into pooled
                #pragma unroll
                for (int c = 0; c < 8; c++) {
                    float s = 0.f;
                    #pragma unroll
                    for (int r = 0; r < 8; r++) s += acc[r][c];
                    s += 8.f * bias[tx * 8 + c];   // 8 rows per thread carry bias
                    atomicAdd(&pooled[tx * 8 + c], s);
                }
                __syncthreads();
            }
        }
    }
    g_pooled[bi * HID_ + tid] = pooled[tid] * (1.f / 128.f);
}

// ---------------------------------------------------------------------------
// Decoder: out = relu(pooled @ wd1 + bd1) @ wd2 + bd2
// ---------------------------------------------------------------------------
__global__ void dec_kernel(const float* __restrict__ wd1,
                           const float* __restrict__ bd1,
                           const float* __restrict__ wd2,
                           const float* __restrict__ bd2,
                           float* __restrict__ out) {
    __shared__ float p[HID_];
    __shared__ float t[HID_];
    const int row = blockIdx.x;
    const int tid = threadIdx.x;
    p[tid] = g_pooled[row * HID_ + tid];
    __syncthreads();
    float s = 0.f;
    #pragma unroll 8
    for (int k = 0; k < HID_; k++)
        s = fmaf(p[k], wd1[k * HID_ + tid], s);
    t[tid] = fmaxf(s + bd1[tid], 0.f);
    __syncthreads();
    if (tid < INP_) {
        float s2 = 0.f;
        #pragma unroll 8
        for (int k = 0; k < HID_; k++)
            s2 = fmaf(t[k], wd2[k * INP_ + tid], s2);
        out[row * INP_ + tid] = s2 + bd2[tid];
    }
}

// ---------------------------------------------------------------------------
extern "C" void kernel_launch(void* const* d_in, const int* in_sizes, int n_in,
                              void* d_out, int out_size) {
    const float* x0    = (const float*)d_in[0];
    const float* x1    = (const float*)d_in[1];
    const float* x2    = (const float*)d_in[2];
    const float* w_enc = (const float*)d_in[3];
    const float* b_enc = (const float*)d_in[4];
    const float* w1    = (const float*)d_in[5];
    const float* b1    = (const float*)d_in[6];
    const float* w2    = (const float*)d_in[7];
    const float* b2    = (const float*)d_in[8];
    const float* w3    = (const float*)d_in[9];
    const float* b3    = (const float*)d_in[10];
    const float* wd1   = (const float*)d_in[11];
    const float* bd1   = (const float*)d_in[12];
    const float* wd2   = (const float*)d_in[13];
    const float* bd2   = (const float*)d_in[14];
    float* out = (float*)d_out;

    cudaFuncSetAttribute(main_kernel,
                         cudaFuncAttributeMaxDynamicSharedMemorySize, SMEM_BYTES);

    enc_kernel<<<ROWS_, 256>>>(x0, x1, x2, w_enc);
    main_kernel<<<ROWS_, dim3(32, 8), SMEM_BYTES>>>(b_enc, w1, b1, w2, b2, w3, b3);
    dec_kernel<<<ROWS_, 256>>>(wd1, bd1, wd2, bd2, out);
}

// round 5
// speedup vs baseline: 4.2929x; 4.2929x over previous
#include <cuda_runtime.h>
#include <cstdint>

#define B_   8
#define OBJ_ 128
#define INP_ 64
#define HID_ 256
#define D_   192
#define ROWS_ (B_*OBJ_)   // 1024

// ---------------- device scratch (allocation-free) ----------------
__device__ __align__(256) float g_ea[ROWS_ * HID_];
__device__ __align__(256) float g_eb[ROWS_ * HID_];
__device__ __align__(256) float g_hbar[ROWS_ * HID_];     // mean_j relu(H2)
__device__ __align__(256) float g_w12[2 * HID_ * HID_];   // tf32-rounded W1, W2

// ---------------- helpers ----------------
__device__ __forceinline__ uint32_t smem_u32(const void* p) {
    uint32_t a;
    asm("{ .reg .u64 t; cvta.to.shared.u64 t, %1; cvt.u32.u64 %0, t; }" : "=r"(a) : "l"(p));
    return a;
}
__device__ __forceinline__ uint32_t tf32_rna(float f) {
    uint32_t r;
    asm("cvt.rna.tf32.f32 %0, %1;" : "=r"(r) : "f"(f));
    return r;
}
__device__ __forceinline__ void mma_tf32(float d[4], const uint32_t a[4],
                                         uint32_t b0, uint32_t b1) {
    asm volatile(
        "mma.sync.aligned.m16n8k8.row.col.f32.tf32.tf32.f32 "
        "{%0,%1,%2,%3}, {%4,%5,%6,%7}, {%8,%9}, {%0,%1,%2,%3};"
        : "+f"(d[0]), "+f"(d[1]), "+f"(d[2]), "+f"(d[3])
        : "r"(a[0]), "r"(a[1]), "r"(a[2]), "r"(a[3]), "r"(b0), "r"(b1));
}
#define CP_ASYNC16(dst, src) \
    asm volatile("cp.async.cg.shared.global [%0], [%1], 16;" :: "r"(dst), "l"(src))
#define CP_COMMIT() asm volatile("cp.async.commit_group;" ::: "memory")
#define CP_WAIT(n)  asm volatile("cp.async.wait_group %0;" :: "n"(n) : "memory")

#define APAD 260            // A rows padded: conflict-free a-frag LDS
#define BPAD 264            // B rows padded: conflict-free b-frag LDS
#define BUFV (32 * BPAD)    // one 32-k-row weight chunk (floats)

// ---------------------------------------------------------------------------
// Prep: round W1,W2 to tf32 (row-major [K,N]) so staging is pure cp.async
// ---------------------------------------------------------------------------
__global__ void prep_kernel(const float* __restrict__ w1, const float* __restrict__ w2) {
    int idx = blockIdx.x * 256 + threadIdx.x;          // 65536 total
    g_w12[idx]                 = __uint_as_float(tf32_rna(w1[idx]));
    g_w12[HID_ * HID_ + idx]   = __uint_as_float(tf32_rna(w2[idx]));
}

// ---------------------------------------------------------------------------
// Encoder: 8 rows per CTA (weight reuse), 128 CTAs
// ---------------------------------------------------------------------------
__global__ void __launch_bounds__(256) enc_kernel(const float* __restrict__ x0,
                                                  const float* __restrict__ x1,
                                                  const float* __restrict__ x2,
                                                  const float* __restrict__ w_enc) {
    __shared__ float xs[8][D_];
    const int tid = threadIdx.x;
    const int r0 = blockIdx.x * 8;
    for (int idx = tid; idx < 8 * D_; idx += 256) {
        int r = idx / D_, d = idx % D_;
        int part = d >> 6, dd = d & 63;
        const float* src = (part == 0) ? x0 : ((part == 1) ? x1 : x2);
        xs[r][d] = src[(r0 + r) * INP_ + dd];
    }
    __syncthreads();
    float sa[8], sb[8];
    #pragma unroll
    for (int r = 0; r < 8; r++) { sa[r] = 0.f; sb[r] = 0.f; }
    for (int d = 0; d < D_; d++) {
        float wa = w_enc[d * HID_ + tid];
        float wb = w_enc[(D_ + d) * HID_ + tid];
        #pragma unroll
        for (int r = 0; r < 8; r++) {
            sa[r] = fmaf(xs[r][d], wa, sa[r]);
            sb[r] = fmaf(xs[r][d], wb, sb[r]);
        }
    }
    #pragma unroll
    for (int r = 0; r < 8; r++) {
        g_ea[(r0 + r) * HID_ + tid] = sa[r];
        g_eb[(r0 + r) * HID_ + tid] = sb[r];
    }
}

// ---------------------------------------------------------------------------
// One 64x256 @ 256x256 layer on tf32 HMMA.
// As: [64][APAD] tf32 activations. gW: tf32 [256][256] row-major.
// POOL=false: Ad <- tf32(relu(out+bias)).  POOL=true: pooled += col-sums of relu(out+bias).
// ---------------------------------------------------------------------------
template <bool POOL>
__device__ __forceinline__ void run_layer(const float* __restrict__ As,
                                          float* __restrict__ Ad,
                                          const float* __restrict__ gW,
                                          const float* __restrict__ bias,
                                          float* __restrict__ pooled,
                                          float* __restrict__ Bs, uint32_t bs_u,
                                          int tid, int wm, int wn, int gid, int tig) {
    float d[2][8][4];
    #pragma unroll
    for (int mf = 0; mf < 2; mf++)
        #pragma unroll
        for (int nf = 0; nf < 8; nf++)
            #pragma unroll
            for (int q = 0; q < 4; q++) d[mf][nf][q] = 0.f;

    // stage chunk 0
    {
        const float4* src = (const float4*)gW;
        #pragma unroll
        for (int i = 0; i < 8; i++) {
            int t4 = tid + i * 256;
            int row = t4 >> 6, c4 = t4 & 63;
            CP_ASYNC16(bs_u + (uint32_t)(row * BPAD + c4 * 4) * 4u, src + t4);
        }
        CP_COMMIT();
    }

    #pragma unroll 1
    for (int kc = 0; kc < 8; kc++) {
        if (kc < 7) {
            const float4* src = (const float4*)(gW + (kc + 1) * 32 * HID_);
            uint32_t boff = (uint32_t)(((kc + 1) & 1) * BUFV) * 4u;
            #pragma unroll
            for (int i = 0; i < 8; i++) {
                int t4 = tid + i * 256;
                int row = t4 >> 6, c4 = t4 & 63;
                CP_ASYNC16(bs_u + boff + (uint32_t)(row * BPAD + c4 * 4) * 4u, src + t4);
            }
            CP_COMMIT();
            CP_WAIT(1);
        } else {
            CP_WAIT(0);
        }
        __syncthreads();

        const float* Bb = Bs + (kc & 1) * BUFV;
        const int mrow0 = wm * 32 + gid;
        const int kbase = kc * 32;                 // <<< FIX: A column chunk base
        #pragma unroll
        for (int ks = 0; ks < 4; ks++) {
            const int kb = ks * 8;
            uint32_t a[2][4];
            #pragma unroll
            for (int mf = 0; mf < 2; mf++) {
                const int r = mrow0 + mf * 16;
                a[mf][0] = __float_as_uint(As[r * APAD + kbase + kb + tig]);
                a[mf][1] = __float_as_uint(As[(r + 8) * APAD + kbase + kb + tig]);
                a[mf][2] = __float_as_uint(As[r * APAD + kbase + kb + tig + 4]);
                a[mf][3] = __float_as_uint(As[(r + 8) * APAD + kbase + kb + tig + 4]);
            }
            #pragma unroll
            for (int nf = 0; nf < 8; nf++) {
                const int cn = wn * 64 + nf * 8 + gid;
                uint32_t b0 = __float_as_uint(Bb[(kb + tig) * BPAD + cn]);
                uint32_t b1 = __float_as_uint(Bb[(kb + tig + 4) * BPAD + cn]);
                mma_tf32(d[0][nf], a[0], b0, b1);
                mma_tf32(d[1][nf], a[1], b0, b1);
            }
        }
        __syncthreads();
    }

    if (!POOL) {
        #pragma unroll
        for (int mf = 0; mf < 2; mf++) {
            const int r0 = wm * 32 + mf * 16 + gid;
            #pragma unroll
            for (int nf = 0; nf < 8; nf++) {
                const int c = wn * 64 + nf * 8 + 2 * tig;
                float2 v0, v1;
                v0.x = __uint_as_float(tf32_rna(fmaxf(d[mf][nf][0] + bias[c], 0.f)));
                v0.y = __uint_as_float(tf32_rna(fmaxf(d[mf][nf][1] + bias[c + 1], 0.f)));
                v1.x = __uint_as_float(tf32_rna(fmaxf(d[mf][nf][2] + bias[c], 0.f)));
                v1.y = __uint_as_float(tf32_rna(fmaxf(d[mf][nf][3] + bias[c + 1], 0.f)));
                *(float2*)&Ad[r0 * APAD + c]       = v0;
                *(float2*)&Ad[(r0 + 8) * APAD + c] = v1;
            }
        }
    } else {
        #pragma unroll
        for (int nf = 0; nf < 8; nf++) {
            const int c0 = wn * 64 + nf * 8 + 2 * tig;
            const float bc0 = bias[c0], bc1 = bias[c0 + 1];
            float s0 = 0.f, s1 = 0.f;
            #pragma unroll
            for (int mf = 0; mf < 2; mf++) {
                s0 += fmaxf(d[mf][nf][0] + bc0, 0.f) + fmaxf(d[mf][nf][2] + bc0, 0.f);
                s1 += fmaxf(d[mf][nf][1] + bc1, 0.f) + fmaxf(d[mf][nf][3] + bc1, 0.f);
            }
            #pragma unroll
            for (int off = 4; off < 32; off <<= 1) {
                s0 += __shfl_xor_sync(0xFFFFFFFFu, s0, off);
                s1 += __shfl_xor_sync(0xFFFFFFFFu, s1, off);
            }
            if (gid == 0) {
                atomicAdd(&pooled[c0], s0);
                atomicAdd(&pooled[c0 + 1], s1);
            }
        }
    }
}

// ---------------------------------------------------------------------------
// Main: one CTA per (b,i); 2 passes of 64 j-rows; 2 tf32-HMMA layers + pooling
// ---------------------------------------------------------------------------
#define SMEM_FLOATS (2 * 64 * APAD + 2 * BUFV + 5 * HID_)
#define SMEM_DYN    (SMEM_FLOATS * 4)

__global__ void __launch_bounds__(256, 1)
main_kernel(const float* __restrict__ b_enc,
            const float* __restrict__ b1, const float* __restrict__ b2) {
    extern __shared__ float sm[];
    float* A0     = sm;                     // 64*APAD
    float* A1     = A0 + 64 * APAD;         // 64*APAD
    float* Bs     = A1 + 64 * APAD;         // 2*BUFV
    float* pooled = Bs + 2 * BUFV;          // 256
    float* ea_s   = pooled + HID_;
    float* sbenc  = ea_s + HID_;
    float* sb1    = sbenc + HID_;
    float* sb2    = sb1 + HID_;

    const int tid  = threadIdx.x;
    const int lane = tid & 31;
    const int w    = tid >> 5;
    const int wm   = w & 1;
    const int wn   = w >> 1;
    const int gid  = lane >> 2;
    const int tig  = lane & 3;
    const int bi   = blockIdx.x;
    const int b    = bi >> 7;
    const uint32_t bs_u = smem_u32(Bs);

    ea_s[tid]   = g_ea[bi * HID_ + tid];
    sbenc[tid]  = b_enc[tid];
    sb1[tid]    = b1[tid];
    sb2[tid]    = b2[tid];
    pooled[tid] = 0.f;
    __syncthreads();

    #pragma unroll 1
    for (int p = 0; p < 2; p++) {
        const int j0 = p * 64;
        // ---- build A0 = tf32(relu(ea_i + eb_j + b_enc)) ----
        const float4* ebr = (const float4*)(g_eb + (b * OBJ_ + j0) * HID_);
        #pragma unroll
        for (int i = 0; i < 16; i++) {
            int idx = tid + i * 256;           // over 4096 float4
            int r = idx >> 6, c4 = idx & 63;
            float4 e = ebr[r * 64 + c4];
            int c = c4 * 4;
            A0[r * APAD + c + 0] = __uint_as_float(tf32_rna(fmaxf(ea_s[c + 0] + e.x + sbenc[c + 0], 0.f)));
            A0[r * APAD + c + 1] = __uint_as_float(tf32_rna(fmaxf(ea_s[c + 1] + e.y + sbenc[c + 1], 0.f)));
            A0[r * APAD + c + 2] = __uint_as_float(tf32_rna(fmaxf(ea_s[c + 2] + e.z + sbenc[c + 2], 0.f)));
            A0[r * APAD + c + 3] = __uint_as_float(tf32_rna(fmaxf(ea_s[c + 3] + e.w + sbenc[c + 3], 0.f)));
        }
        __syncthreads();

        run_layer<false>(A0, A1, g_w12, sb1, pooled, Bs, bs_u, tid, wm, wn, gid, tig);
        __syncthreads();
        run_layer<true>(A1, nullptr, g_w12 + HID_ * HID_, sb2, pooled, Bs, bs_u,
                        tid, wm, wn, gid, tig);
        __syncthreads();
    }

    g_hbar[bi * HID_ + tid] = pooled[tid] * (1.f / 128.f);
}

// ---------------------------------------------------------------------------
// Dec: pooled = hbar @ w3 + b3; out = relu(pooled @ wd1 + bd1) @ wd2 + bd2
// ---------------------------------------------------------------------------
__global__ void __launch_bounds__(256) dec_kernel(const float* __restrict__ w3,
                                                  const float* __restrict__ b3,
                                                  const float* __restrict__ wd1,
                                                  const float* __restrict__ bd1,
                                                  const float* __restrict__ wd2,
                                                  const float* __restrict__ bd2,
                                                  float* __restrict__ out) {
    __shared__ float hb[8][HID_];
    __shared__ float pl[8][HID_];
    const int tid = threadIdx.x;
    const int r0 = blockIdx.x * 8;

    for (int idx = tid; idx < 8 * HID_; idx += 256)
        hb[idx >> 8][idx & 255] = g_hbar[(r0 + (idx >> 8)) * HID_ + (idx & 255)];
    __syncthreads();

    float acc[8];
    #pragma unroll
    for (int r = 0; r < 8; r++) acc[r] = 0.f;
    for (int k = 0; k < HID_; k++) {
        float w = w3[k * HID_ + tid];
        #pragma unroll
        for (int r = 0; r < 8; r++) acc[r] = fmaf(hb[r][k], w, acc[r]);
    }
    #pragma unroll
    for (int r = 0; r < 8; r++) pl[r][tid] = acc[r] + b3[tid];
    __syncthreads();

    #pragma unroll
    for (int r = 0; r < 8; r++) acc[r] = 0.f;
    for (int k = 0; k < HID_; k++) {
        float w = wd1[k * HID_ + tid];
        #pragma unroll
        for (int r = 0; r < 8; r++) acc[r] = fmaf(pl[r][k], w, acc[r]);
    }
    __syncthreads();
    #pragma unroll
    for (int r = 0; r < 8; r++) hb[r][tid] = fmaxf(acc[r] + bd1[tid], 0.f);
    __syncthreads();

    const int c = tid & 63, rr = tid >> 6;
    float o0 = 0.f, o1 = 0.f;
    for (int k = 0; k < HID_; k++) {
        float w = wd2[k * INP_ + c];
        o0 = fmaf(hb[rr][k], w, o0);
        o1 = fmaf(hb[rr + 4][k], w, o1);
    }
    out[(r0 + rr) * INP_ + c]     = o0 + bd2[c];
    out[(r0 + rr + 4) * INP_ + c] = o1 + bd2[c];
}

// ---------------------------------------------------------------------------
extern "C" void kernel_launch(void* const* d_in, const int* in_sizes, int n_in,
                              void* d_out, int out_size) {
    const float* x0    = (const float*)d_in[0];
    const float* x1    = (const float*)d_in[1];
    const float* x2    = (const float*)d_in[2];
    const float* w_enc = (const float*)d_in[3];
    const float* b_enc = (const float*)d_in[4];
    const float* w1    = (const float*)d_in[5];
    const float* b1    = (const float*)d_in[6];
    const float* w2    = (const float*)d_in[7];
    const float* b2    = (const float*)d_in[8];
    const float* w3    = (const float*)d_in[9];
    const float* b3    = (const float*)d_in[10];
    const float* wd1   = (const float*)d_in[11];
    const float* bd1   = (const float*)d_in[12];
    const float* wd2   = (const float*)d_in[13];
    const float* bd2   = (const float*)d_in[14];
    float* out = (float*)d_out;

    cudaFuncSetAttribute(main_kernel,
                         cudaFuncAttributeMaxDynamicSharedMemorySize, SMEM_DYN);

    prep_kernel<<<256, 256>>>(w1, w2);
    enc_kernel<<<ROWS_ / 8, 256>>>(x0, x1, x2, w_enc);
    main_kernel<<<ROWS_, 256, SMEM_DYN>>>(b_enc, b1, b2);
    dec_kernel<<<ROWS_ / 8, 256>>>(w3, b3, wd1, bd1, wd2, bd2, out);
}

// round 6
// speedup vs baseline: 4.7732x; 1.1119x over previous
#include <cuda_runtime.h>
#include <cstdint>

#define B_   8
#define OBJ_ 128
#define INP_ 64
#define HID_ 256
#define D_   192
#define ROWS_ (B_*OBJ_)   // 1024

// ---------------- device scratch (allocation-free) ----------------
__device__ __align__(256) float g_ea[ROWS_ * HID_];
__device__ __align__(256) float g_eb[ROWS_ * HID_];
__device__ __align__(256) float g_hbar[ROWS_ * HID_];     // mean_j relu(H2)
__device__ __align__(256) float g_w12[2 * HID_ * HID_];   // tf32-rounded W1, W2

// ---------------- helpers ----------------
__device__ __forceinline__ uint32_t smem_u32(const void* p) {
    uint32_t a;
    asm("{ .reg .u64 t; cvta.to.shared.u64 t, %1; cvt.u32.u64 %0, t; }" : "=r"(a) : "l"(p));
    return a;
}
__device__ __forceinline__ uint32_t tf32_rna(float f) {
    uint32_t r;
    asm("cvt.rna.tf32.f32 %0, %1;" : "=r"(r) : "f"(f));
    return r;
}
__device__ __forceinline__ void mma_tf32(float d[4], const uint32_t a[4],
                                         uint32_t b0, uint32_t b1) {
    asm volatile(
        "mma.sync.aligned.m16n8k8.row.col.f32.tf32.tf32.f32 "
        "{%0,%1,%2,%3}, {%4,%5,%6,%7}, {%8,%9}, {%0,%1,%2,%3};"
        : "+f"(d[0]), "+f"(d[1]), "+f"(d[2]), "+f"(d[3])
        : "r"(a[0]), "r"(a[1]), "r"(a[2]), "r"(a[3]), "r"(b0), "r"(b1));
}
#define CP_ASYNC16(dst, src) \
    asm volatile("cp.async.cg.shared.global [%0], [%1], 16;" :: "r"(dst), "l"(src))
#define CP_COMMIT() asm volatile("cp.async.commit_group;" ::: "memory")
#define CP_WAIT(n)  asm volatile("cp.async.wait_group %0;" :: "n"(n) : "memory")

#define APAD 260            // A rows padded: conflict-free a-frag LDS
#define BPAD 264            // B rows padded: conflict-free b-frag LDS
#define BUFV (32 * BPAD)    // one 32-k-row weight chunk (floats)

// ---------------------------------------------------------------------------
// Prep: round W1,W2 to tf32 (row-major [K,N])
// ---------------------------------------------------------------------------
__global__ void prep_kernel(const float* __restrict__ w1, const float* __restrict__ w2) {
    int idx = blockIdx.x * 256 + threadIdx.x;          // 65536 total
    g_w12[idx]               = __uint_as_float(tf32_rna(w1[idx]));
    g_w12[HID_ * HID_ + idx] = __uint_as_float(tf32_rna(w2[idx]));
}

// ---------------------------------------------------------------------------
// Encoder: 8 rows per CTA, manual k-unroll for MLP
// ---------------------------------------------------------------------------
__global__ void __launch_bounds__(256) enc_kernel(const float* __restrict__ x0,
                                                  const float* __restrict__ x1,
                                                  const float* __restrict__ x2,
                                                  const float* __restrict__ w_enc) {
    __shared__ float xs[8][D_];
    const int tid = threadIdx.x;
    const int r0 = blockIdx.x * 8;
    for (int idx = tid; idx < 8 * D_; idx += 256) {
        int r = idx / D_, d = idx % D_;
        int part = d >> 6, dd = d & 63;
        const float* src = (part == 0) ? x0 : ((part == 1) ? x1 : x2);
        xs[r][d] = src[(r0 + r) * INP_ + dd];
    }
    __syncthreads();
    float sa[8], sb[8];
    #pragma unroll
    for (int r = 0; r < 8; r++) { sa[r] = 0.f; sb[r] = 0.f; }
    #pragma unroll 1
    for (int d0 = 0; d0 < D_; d0 += 4) {
        float wa[4], wb[4];
        #pragma unroll
        for (int q = 0; q < 4; q++) {
            wa[q] = w_enc[(d0 + q) * HID_ + tid];
            wb[q] = w_enc[(D_ + d0 + q) * HID_ + tid];
        }
        #pragma unroll
        for (int q = 0; q < 4; q++)
            #pragma unroll
            for (int r = 0; r < 8; r++) {
                sa[r] = fmaf(xs[r][d0 + q], wa[q], sa[r]);
                sb[r] = fmaf(xs[r][d0 + q], wb[q], sb[r]);
            }
    }
    #pragma unroll
    for (int r = 0; r < 8; r++) {
        g_ea[(r0 + r) * HID_ + tid] = sa[r];
        g_eb[(r0 + r) * HID_ + tid] = sb[r];
    }
}

// ---------------------------------------------------------------------------
// One 128x256 @ 256x256 layer on tf32 HMMA. A in/out IN PLACE (As), 8 warps
// as 2(M:64 rows)x4(N:64 cols); warp tile 64x64 -> d[4][8][4] = 128 accum.
// POOL=false: As <- tf32(relu(out+bias)). POOL=true: pooled += colsum relu.
// ---------------------------------------------------------------------------
template <bool POOL>
__device__ __forceinline__ void run_layer(float* __restrict__ As,
                                          const float* __restrict__ gW,
                                          const float* __restrict__ bias,
                                          float* __restrict__ pooled,
                                          float* __restrict__ Bs, uint32_t bs_u,
                                          int tid, int wm, int wn, int gid, int tig) {
    float d[4][8][4];
    #pragma unroll
    for (int mf = 0; mf < 4; mf++)
        #pragma unroll
        for (int nf = 0; nf < 8; nf++)
            #pragma unroll
            for (int q = 0; q < 4; q++) d[mf][nf][q] = 0.f;

    // stage chunk 0
    {
        const float4* src = (const float4*)gW;
        #pragma unroll
        for (int i = 0; i < 8; i++) {
            int t4 = tid + i * 256;
            int row = t4 >> 6, c4 = t4 & 63;
            CP_ASYNC16(bs_u + (uint32_t)(row * BPAD + c4 * 4) * 4u, src + t4);
        }
        CP_COMMIT();
    }

    #pragma unroll 1
    for (int kc = 0; kc < 8; kc++) {
        if (kc < 7) {
            const float4* src = (const float4*)(gW + (kc + 1) * 32 * HID_);
            uint32_t boff = (uint32_t)(((kc + 1) & 1) * BUFV) * 4u;
            #pragma unroll
            for (int i = 0; i < 8; i++) {
                int t4 = tid + i * 256;
                int row = t4 >> 6, c4 = t4 & 63;
                CP_ASYNC16(bs_u + boff + (uint32_t)(row * BPAD + c4 * 4) * 4u, src + t4);
            }
            CP_COMMIT();
            CP_WAIT(1);
        } else {
            CP_WAIT(0);
        }
        __syncthreads();

        const float* Bb = Bs + (kc & 1) * BUFV;
        const int mrow0 = wm * 64 + gid;
        const int kbase = kc * 32;
        #pragma unroll
        for (int ks = 0; ks < 4; ks++) {
            const int kb = kbase + ks * 8;
            uint32_t a[4][4];
            #pragma unroll
            for (int mf = 0; mf < 4; mf++) {
                const int r = mrow0 + mf * 16;
                a[mf][0] = __float_as_uint(As[r * APAD + kb + tig]);
                a[mf][1] = __float_as_uint(As[(r + 8) * APAD + kb + tig]);
                a[mf][2] = __float_as_uint(As[r * APAD + kb + tig + 4]);
                a[mf][3] = __float_as_uint(As[(r + 8) * APAD + kb + tig + 4]);
            }
            #pragma unroll
            for (int nf = 0; nf < 8; nf++) {
                const int cn = wn * 64 + nf * 8 + gid;
                uint32_t b0 = __float_as_uint(Bb[(ks * 8 + tig) * BPAD + cn]);
                uint32_t b1 = __float_as_uint(Bb[(ks * 8 + tig + 4) * BPAD + cn]);
                #pragma unroll
                for (int mf = 0; mf < 4; mf++)
                    mma_tf32(d[mf][nf], a[mf], b0, b1);
            }
        }
        __syncthreads();
    }
    // all reads of As are done (barrier above) -> in-place epilogue is safe

    if (!POOL) {
        #pragma unroll
        for (int mf = 0; mf < 4; mf++) {
            const int r0 = wm * 64 + mf * 16 + gid;
            #pragma unroll
            for (int nf = 0; nf < 8; nf++) {
                const int c = wn * 64 + nf * 8 + 2 * tig;
                float2 v0, v1;
                v0.x = __uint_as_float(tf32_rna(fmaxf(d[mf][nf][0] + bias[c], 0.f)));
                v0.y = __uint_as_float(tf32_rna(fmaxf(d[mf][nf][1] + bias[c + 1], 0.f)));
                v1.x = __uint_as_float(tf32_rna(fmaxf(d[mf][nf][2] + bias[c], 0.f)));
                v1.y = __uint_as_float(tf32_rna(fmaxf(d[mf][nf][3] + bias[c + 1], 0.f)));
                *(float2*)&As[r0 * APAD + c]       = v0;
                *(float2*)&As[(r0 + 8) * APAD + c] = v1;
            }
        }
    } else {
        #pragma unroll
        for (int nf = 0; nf < 8; nf++) {
            const int c0 = wn * 64 + nf * 8 + 2 * tig;
            const float bc0 = bias[c0], bc1 = bias[c0 + 1];
            float s0 = 0.f, s1 = 0.f;
            #pragma unroll
            for (int mf = 0; mf < 4; mf++) {
                s0 += fmaxf(d[mf][nf][0] + bc0, 0.f) + fmaxf(d[mf][nf][2] + bc0, 0.f);
                s1 += fmaxf(d[mf][nf][1] + bc1, 0.f) + fmaxf(d[mf][nf][3] + bc1, 0.f);
            }
            #pragma unroll
            for (int off = 4; off < 32; off <<= 1) {
                s0 += __shfl_xor_sync(0xFFFFFFFFu, s0, off);
                s1 += __shfl_xor_sync(0xFFFFFFFFu, s1, off);
            }
            if (gid == 0) {
                atomicAdd(&pooled[c0], s0);
                atomicAdd(&pooled[c0 + 1], s1);
            }
        }
    }
}

// ---------------------------------------------------------------------------
// Main: one CTA per (b,i); SINGLE pass over all 128 j-rows.
// ---------------------------------------------------------------------------
#define SMEM_FLOATS (128 * APAD + 2 * BUFV + 5 * HID_)
#define SMEM_DYN    (SMEM_FLOATS * 4)

__global__ void __launch_bounds__(256, 1)
main_kernel(const float* __restrict__ b_enc,
            const float* __restrict__ b1, const float* __restrict__ b2) {
    extern __shared__ float sm[];
    float* A0     = sm;                     // 128*APAD
    float* Bs     = A0 + 128 * APAD;        // 2*BUFV
    float* pooled = Bs + 2 * BUFV;          // 256
    float* ea_s   = pooled + HID_;
    float* sbenc  = ea_s + HID_;
    float* sb1    = sbenc + HID_;
    float* sb2    = sb1 + HID_;

    const int tid  = threadIdx.x;
    const int lane = tid & 31;
    const int w    = tid >> 5;
    const int wm   = w & 1;
    const int wn   = w >> 1;
    const int gid  = lane >> 2;
    const int tig  = lane & 3;
    const int bi   = blockIdx.x;
    const int b    = bi >> 7;
    const uint32_t bs_u = smem_u32(Bs);

    ea_s[tid]   = g_ea[bi * HID_ + tid];
    sbenc[tid]  = b_enc[tid];
    sb1[tid]    = b1[tid];
    sb2[tid]    = b2[tid];
    pooled[tid] = 0.f;
    __syncthreads();

    // ---- build A0 = tf32(relu(ea_i + eb_j + b_enc)) for all 128 j ----
    const float4* ebr = (const float4*)(g_eb + (b * OBJ_) * HID_);
    #pragma unroll
    for (int i = 0; i < 32; i++) {
        int idx = tid + i * 256;           // over 8192 float4
        int r = idx >> 6, c4 = idx & 63;
        float4 e = ebr[idx];
        int c = c4 * 4;
        A0[r * APAD + c + 0] = __uint_as_float(tf32_rna(fmaxf(ea_s[c + 0] + e.x + sbenc[c + 0], 0.f)));
        A0[r * APAD + c + 1] = __uint_as_float(tf32_rna(fmaxf(ea_s[c + 1] + e.y + sbenc[c + 1], 0.f)));
        A0[r * APAD + c + 2] = __uint_as_float(tf32_rna(fmaxf(ea_s[c + 2] + e.z + sbenc[c + 2], 0.f)));
        A0[r * APAD + c + 3] = __uint_as_float(tf32_rna(fmaxf(ea_s[c + 3] + e.w + sbenc[c + 3], 0.f)));
    }
    __syncthreads();

    run_layer<false>(A0, g_w12, sb1, pooled, Bs, bs_u, tid, wm, wn, gid, tig);
    __syncthreads();
    run_layer<true>(A0, g_w12 + HID_ * HID_, sb2, pooled, Bs, bs_u,
                    tid, wm, wn, gid, tig);
    __syncthreads();

    g_hbar[bi * HID_ + tid] = pooled[tid] * (1.f / 128.f);
}

// ---------------------------------------------------------------------------
// Dec: pooled = hbar @ w3 + b3; out = relu(pooled @ wd1 + bd1) @ wd2 + bd2
// manual k-unroll (MLP=8)
// ---------------------------------------------------------------------------
__global__ void __launch_bounds__(256) dec_kernel(const float* __restrict__ w3,
                                                  const float* __restrict__ b3,
                                                  const float* __restrict__ wd1,
                                                  const float* __restrict__ bd1,
                                                  const float* __restrict__ wd2,
                                                  const float* __restrict__ bd2,
                                                  float* __restrict__ out) {
    __shared__ float hb[8][HID_];
    __shared__ float pl[8][HID_];
    const int tid = threadIdx.x;
    const int r0 = blockIdx.x * 8;

    for (int idx = tid; idx < 8 * HID_; idx += 256)
        hb[idx >> 8][idx & 255] = g_hbar[(r0 + (idx >> 8)) * HID_ + (idx & 255)];
    __syncthreads();

    float acc[8];
    #pragma unroll
    for (int r = 0; r < 8; r++) acc[r] = 0.f;
    #pragma unroll 1
    for (int k0 = 0; k0 < HID_; k0 += 8) {
        float wv[8];
        #pragma unroll
        for (int q = 0; q < 8; q++) wv[q] = w3[(k0 + q) * HID_ + tid];
        #pragma unroll
        for (int q = 0; q < 8; q++)
            #pragma unroll
            for (int r = 0; r < 8; r++) acc[r] = fmaf(hb[r][k0 + q], wv[q], acc[r]);
    }
    #pragma unroll
    for (int r = 0; r < 8; r++) pl[r][tid] = acc[r] + b3[tid];
    __syncthreads();

    #pragma unroll
    for (int r = 0; r < 8; r++) acc[r] = 0.f;
    #pragma unroll 1
    for (int k0 = 0; k0 < HID_; k0 += 8) {
        float wv[8];
        #pragma unroll
        for (int q = 0; q < 8; q++) wv[q] = wd1[(k0 + q) * HID_ + tid];
        #pragma unroll
        for (int q = 0; q < 8; q++)
            #pragma unroll
            for (int r = 0; r < 8; r++) acc[r] = fmaf(pl[r][k0 + q], wv[q], acc[r]);
    }
    __syncthreads();
    #pragma unroll
    for (int r = 0; r < 8; r++) hb[r][tid] = fmaxf(acc[r] + bd1[tid], 0.f);
    __syncthreads();

    const int c = tid & 63, rr = tid >> 6;
    float o0 = 0.f, o1 = 0.f;
    #pragma unroll 1
    for (int k0 = 0; k0 < HID_; k0 += 8) {
        float wv[8];
        #pragma unroll
        for (int q = 0; q < 8; q++) wv[q] = wd2[(k0 + q) * INP_ + c];
        #pragma unroll
        for (int q = 0; q < 8; q++) {
            o0 = fmaf(hb[rr][k0 + q], wv[q], o0);
            o1 = fmaf(hb[rr + 4][k0 + q], wv[q], o1);
        }
    }
    out[(r0 + rr) * INP_ + c]     = o0 + bd2[c];
    out[(r0 + rr + 4) * INP_ + c] = o1 + bd2[c];
}

// ---------------------------------------------------------------------------
extern "C" void kernel_launch(void* const* d_in, const int* in_sizes, int n_in,
                              void* d_out, int out_size) {
    const float* x0    = (const float*)d_in[0];
    const float* x1    = (const float*)d_in[1];
    const float* x2    = (const float*)d_in[2];
    const float* w_enc = (const float*)d_in[3];
    const float* b_enc = (const float*)d_in[4];
    const float* w1    = (const float*)d_in[5];
    const float* b1    = (const float*)d_in[6];
    const float* w2    = (const float*)d_in[7];
    const float* b2    = (const float*)d_in[8];
    const float* w3    = (const float*)d_in[9];
    const float* b3    = (const float*)d_in[10];
    const float* wd1   = (const float*)d_in[11];
    const float* bd1   = (const float*)d_in[12];
    const float* wd2   = (const float*)d_in[13];
    const float* bd2   = (const float*)d_in[14];
    float* out = (float*)d_out;

    cudaFuncSetAttribute(main_kernel,
                         cudaFuncAttributeMaxDynamicSharedMemorySize, SMEM_DYN);

    prep_kernel<<<256, 256>>>(w1, w2);
    enc_kernel<<<ROWS_ / 8, 256>>>(x0, x1, x2, w_enc);
    main_kernel<<<ROWS_, 256, SMEM_DYN>>>(b_enc, b1, b2);
    dec_kernel<<<ROWS_ / 8, 256>>>(w3, b3, wd1, bd1, wd2, bd2, out);
}

// round 7
// speedup vs baseline: 4.8387x; 1.0137x over previous
#include <cuda_runtime.h>
#include <cstdint>

#define B_   8
#define OBJ_ 128
#define INP_ 64
#define HID_ 256
#define D_   192
#define ROWS_ (B_*OBJ_)   // 1024

// ---------------- device scratch (allocation-free) ----------------
__device__ __align__(256) float g_ea[ROWS_ * HID_];
__device__ __align__(256) float g_eb[ROWS_ * HID_];
__device__ __align__(256) float g_hbar[ROWS_ * HID_];     // mean_j relu(H2)
__device__ __align__(256) float g_w12[2 * HID_ * HID_];   // tf32-rounded W1, W2
__device__ __align__(256) float g_w34[HID_ * HID_];       // w3 @ wd1 (fp32)
__device__ __align__(256) float g_b34[HID_];              // b3 @ wd1 + bd1

// ---------------- helpers ----------------
__device__ __forceinline__ uint32_t smem_u32(const void* p) {
    uint32_t a;
    asm("{ .reg .u64 t; cvta.to.shared.u64 t, %1; cvt.u32.u64 %0, t; }" : "=r"(a) : "l"(p));
    return a;
}
__device__ __forceinline__ uint32_t tf32_rna(float f) {
    uint32_t r;
    asm("cvt.rna.tf32.f32 %0, %1;" : "=r"(r) : "f"(f));
    return r;
}
__device__ __forceinline__ void mma_tf32(float d[4], const uint32_t a[4],
                                         uint32_t b0, uint32_t b1) {
    asm volatile(
        "mma.sync.aligned.m16n8k8.row.col.f32.tf32.tf32.f32 "
        "{%0,%1,%2,%3}, {%4,%5,%6,%7}, {%8,%9}, {%0,%1,%2,%3};"
        : "+f"(d[0]), "+f"(d[1]), "+f"(d[2]), "+f"(d[3])
        : "r"(a[0]), "r"(a[1]), "r"(a[2]), "r"(a[3]), "r"(b0), "r"(b1));
}
#define CP_ASYNC16(dst, src) \
    asm volatile("cp.async.cg.shared.global [%0], [%1], 16;" :: "r"(dst), "l"(src))
#define CP_COMMIT() asm volatile("cp.async.commit_group;" ::: "memory")
#define CP_WAIT(n)  asm volatile("cp.async.wait_group %0;" :: "n"(n) : "memory")

#define APAD 260            // A rows padded: conflict-free a-frag LDS
#define BPAD 264            // B rows padded: conflict-free b-frag LDS
#define BUFV (32 * BPAD)    // one 32-k-row weight chunk (floats)

// ---------------------------------------------------------------------------
// Prep A: round W1,W2 to tf32 (row-major [K,N])
// ---------------------------------------------------------------------------
__global__ void prep_kernel(const float* __restrict__ w1, const float* __restrict__ w2) {
    int idx = blockIdx.x * 256 + threadIdx.x;          // 65536 total
    g_w12[idx]               = __uint_as_float(tf32_rna(w1[idx]));
    g_w12[HID_ * HID_ + idx] = __uint_as_float(tf32_rna(w2[idx]));
}

// ---------------------------------------------------------------------------
// Prep B: W34 = w3 @ wd1 ; b34 = b3 @ wd1 + bd1.  grid 257: CTA m<256 -> row m,
// CTA 256 -> bias row.
// ---------------------------------------------------------------------------
__global__ void __launch_bounds__(256) prep_w34_kernel(const float* __restrict__ w3,
                                                       const float* __restrict__ b3,
                                                       const float* __restrict__ wd1,
                                                       const float* __restrict__ bd1) {
    __shared__ float row[HID_];
    const int m = blockIdx.x;
    const int tid = threadIdx.x;
    row[tid] = (m < 256) ? w3[m * HID_ + tid] : b3[tid];
    __syncthreads();
    float acc = 0.f;
    float wv[8];
    #pragma unroll
    for (int q = 0; q < 8; q++) wv[q] = wd1[q * HID_ + tid];
    #pragma unroll 1
    for (int k0 = 0; k0 < HID_; k0 += 8) {
        float wnx[8];
        if (k0 + 8 < HID_) {
            #pragma unroll
            for (int q = 0; q < 8; q++) wnx[q] = wd1[(k0 + 8 + q) * HID_ + tid];
        }
        #pragma unroll
        for (int q = 0; q < 8; q++) acc = fmaf(row[k0 + q], wv[q], acc);
        #pragma unroll
        for (int q = 0; q < 8; q++) wv[q] = wnx[q];
    }
    if (m < 256) g_w34[m * HID_ + tid] = acc;
    else         g_b34[tid] = acc + bd1[tid];
}

// ---------------------------------------------------------------------------
// Encoder: 8 rows per CTA
// ---------------------------------------------------------------------------
__global__ void __launch_bounds__(256) enc_kernel(const float* __restrict__ x0,
                                                  const float* __restrict__ x1,
                                                  const float* __restrict__ x2,
                                                  const float* __restrict__ w_enc) {
    __shared__ float xs[8][D_];
    const int tid = threadIdx.x;
    const int r0 = blockIdx.x * 8;
    for (int idx = tid; idx < 8 * D_; idx += 256) {
        int r = idx / D_, d = idx % D_;
        int part = d >> 6, dd = d & 63;
        const float* src = (part == 0) ? x0 : ((part == 1) ? x1 : x2);
        xs[r][d] = src[(r0 + r) * INP_ + dd];
    }
    __syncthreads();
    float sa[8], sb[8];
    #pragma unroll
    for (int r = 0; r < 8; r++) { sa[r] = 0.f; sb[r] = 0.f; }
    #pragma unroll 1
    for (int d0 = 0; d0 < D_; d0 += 4) {
        float wa[4], wb[4];
        #pragma unroll
        for (int q = 0; q < 4; q++) {
            wa[q] = w_enc[(d0 + q) * HID_ + tid];
            wb[q] = w_enc[(D_ + d0 + q) * HID_ + tid];
        }
        #pragma unroll
        for (int q = 0; q < 4; q++)
            #pragma unroll
            for (int r = 0; r < 8; r++) {
                sa[r] = fmaf(xs[r][d0 + q], wa[q], sa[r]);
                sb[r] = fmaf(xs[r][d0 + q], wb[q], sb[r]);
            }
    }
    #pragma unroll
    for (int r = 0; r < 8; r++) {
        g_ea[(r0 + r) * HID_ + tid] = sa[r];
        g_eb[(r0 + r) * HID_ + tid] = sb[r];
    }
}

// ---------------------------------------------------------------------------
// One 128x256 @ 256x256 layer on tf32 HMMA, 16 warps (4M x 4N), warp tile
// 32x64, in-place on As. POOL=true: pooled += colsum relu(out+bias).
// ---------------------------------------------------------------------------
template <bool POOL>
__device__ __forceinline__ void run_layer(float* __restrict__ As,
                                          const float* __restrict__ gW,
                                          const float* __restrict__ bias,
                                          float* __restrict__ pooled,
                                          float* __restrict__ Bs, uint32_t bs_u,
                                          int tid, int wm, int wn, int gid, int tig) {
    float d[2][8][4];
    #pragma unroll
    for (int mf = 0; mf < 2; mf++)
        #pragma unroll
        for (int nf = 0; nf < 8; nf++)
            #pragma unroll
            for (int q = 0; q < 4; q++) d[mf][nf][q] = 0.f;

    // stage chunk 0
    {
        const float4* src = (const float4*)gW;
        #pragma unroll
        for (int i = 0; i < 4; i++) {
            int t4 = tid + i * 512;
            int row = t4 >> 6, c4 = t4 & 63;
            CP_ASYNC16(bs_u + (uint32_t)(row * BPAD + c4 * 4) * 4u, src + t4);
        }
        CP_COMMIT();
    }

    #pragma unroll 1
    for (int kc = 0; kc < 8; kc++) {
        if (kc < 7) {
            const float4* src = (const float4*)(gW + (kc + 1) * 32 * HID_);
            uint32_t boff = (uint32_t)(((kc + 1) & 1) * BUFV) * 4u;
            #pragma unroll
            for (int i = 0; i < 4; i++) {
                int t4 = tid + i * 512;
                int row = t4 >> 6, c4 = t4 & 63;
                CP_ASYNC16(bs_u + boff + (uint32_t)(row * BPAD + c4 * 4) * 4u, src + t4);
            }
            CP_COMMIT();
            CP_WAIT(1);
        } else {
            CP_WAIT(0);
        }
        __syncthreads();

        const float* Bb = Bs + (kc & 1) * BUFV;
        const int mrow0 = wm * 32 + gid;
        const int kbase = kc * 32;
        #pragma unroll
        for (int ks = 0; ks < 4; ks++) {
            const int kb = kbase + ks * 8;
            uint32_t a[2][4];
            #pragma unroll
            for (int mf = 0; mf < 2; mf++) {
                const int r = mrow0 + mf * 16;
                a[mf][0] = __float_as_uint(As[r * APAD + kb + tig]);
                a[mf][1] = __float_as_uint(As[(r + 8) * APAD + kb + tig]);
                a[mf][2] = __float_as_uint(As[r * APAD + kb + tig + 4]);
                a[mf][3] = __float_as_uint(As[(r + 8) * APAD + kb + tig + 4]);
            }
            #pragma unroll
            for (int nf = 0; nf < 8; nf++) {
                const int cn = wn * 64 + nf * 8 + gid;
                uint32_t b0 = __float_as_uint(Bb[(ks * 8 + tig) * BPAD + cn]);
                uint32_t b1 = __float_as_uint(Bb[(ks * 8 + tig + 4) * BPAD + cn]);
                mma_tf32(d[0][nf], a[0], b0, b1);
                mma_tf32(d[1][nf], a[1], b0, b1);
            }
        }
        __syncthreads();
    }
    // all reads of As done (barrier above) -> in-place epilogue safe

    if (!POOL) {
        #pragma unroll
        for (int mf = 0; mf < 2; mf++) {
            const int r0 = wm * 32 + mf * 16 + gid;
            #pragma unroll
            for (int nf = 0; nf < 8; nf++) {
                const int c = wn * 64 + nf * 8 + 2 * tig;
                float2 v0, v1;
                v0.x = __uint_as_float(tf32_rna(fmaxf(d[mf][nf][0] + bias[c], 0.f)));
                v0.y = __uint_as_float(tf32_rna(fmaxf(d[mf][nf][1] + bias[c + 1], 0.f)));
                v1.x = __uint_as_float(tf32_rna(fmaxf(d[mf][nf][2] + bias[c], 0.f)));
                v1.y = __uint_as_float(tf32_rna(fmaxf(d[mf][nf][3] + bias[c + 1], 0.f)));
                *(float2*)&As[r0 * APAD + c]       = v0;
                *(float2*)&As[(r0 + 8) * APAD + c] = v1;
            }
        }
    } else {
        #pragma unroll
        for (int nf = 0; nf < 8; nf++) {
            const int c0 = wn * 64 + nf * 8 + 2 * tig;
            const float bc0 = bias[c0], bc1 = bias[c0 + 1];
            float s0 = 0.f, s1 = 0.f;
            #pragma unroll
            for (int mf = 0; mf < 2; mf++) {
                s0 += fmaxf(d[mf][nf][0] + bc0, 0.f) + fmaxf(d[mf][nf][2] + bc0, 0.f);
                s1 += fmaxf(d[mf][nf][1] + bc1, 0.f) + fmaxf(d[mf][nf][3] + bc1, 0.f);
            }
            #pragma unroll
            for (int off = 4; off < 32; off <<= 1) {
                s0 += __shfl_xor_sync(0xFFFFFFFFu, s0, off);
                s1 += __shfl_xor_sync(0xFFFFFFFFu, s1, off);
            }
            if (gid == 0) {
                atomicAdd(&pooled[c0], s0);
                atomicAdd(&pooled[c0 + 1], s1);
            }
        }
    }
}

// ---------------------------------------------------------------------------
// Main: one CTA per (b,i); single pass over 128 j-rows; 512 threads.
// ---------------------------------------------------------------------------
#define SMEM_FLOATS (128 * APAD + 2 * BUFV + 5 * HID_)
#define SMEM_DYN    (SMEM_FLOATS * 4)

__global__ void __launch_bounds__(512, 1)
main_kernel(const float* __restrict__ b_enc,
            const float* __restrict__ b1, const float* __restrict__ b2) {
    extern __shared__ float sm[];
    float* A0     = sm;                     // 128*APAD
    float* Bs     = A0 + 128 * APAD;        // 2*BUFV
    float* pooled = Bs + 2 * BUFV;          // 256
    float* ea_s   = pooled + HID_;
    float* sbenc  = ea_s + HID_;
    float* sb1    = sbenc + HID_;
    float* sb2    = sb1 + HID_;

    const int tid  = threadIdx.x;
    const int lane = tid & 31;
    const int w    = tid >> 5;              // 0..15
    const int wm   = w >> 2;                // 0..3 (32-row group)
    const int wn   = w & 3;                 // 0..3 (64-col group)
    const int gid  = lane >> 2;
    const int tig  = lane & 3;
    const int bi   = blockIdx.x;
    const int b    = bi >> 7;
    const uint32_t bs_u = smem_u32(Bs);

    if (tid < 256) {
        ea_s[tid]   = g_ea[bi * HID_ + tid];
        sbenc[tid]  = b_enc[tid];
        sb1[tid]    = b1[tid];
        sb2[tid]    = b2[tid];
        pooled[tid] = 0.f;
    }
    __syncthreads();

    // ---- build A0 = tf32(relu(ea_i + eb_j + b_enc)) for all 128 j ----
    const float4* ebr = (const float4*)(g_eb + (b * OBJ_) * HID_);
    #pragma unroll
    for (int i = 0; i < 16; i++) {
        int idx = tid + i * 512;           // 8192 float4
        int r = idx >> 6, c4 = idx & 63;
        float4 e = ebr[idx];
        int c = c4 * 4;
        A0[r * APAD + c + 0] = __uint_as_float(tf32_rna(fmaxf(ea_s[c + 0] + e.x + sbenc[c + 0], 0.f)));
        A0[r * APAD + c + 1] = __uint_as_float(tf32_rna(fmaxf(ea_s[c + 1] + e.y + sbenc[c + 1], 0.f)));
        A0[r * APAD + c + 2] = __uint_as_float(tf32_rna(fmaxf(ea_s[c + 2] + e.z + sbenc[c + 2], 0.f)));
        A0[r * APAD + c + 3] = __uint_as_float(tf32_rna(fmaxf(ea_s[c + 3] + e.w + sbenc[c + 3], 0.f)));
    }
    __syncthreads();

    run_layer<false>(A0, g_w12, sb1, pooled, Bs, bs_u, tid, wm, wn, gid, tig);
    __syncthreads();
    run_layer<true>(A0, g_w12 + HID_ * HID_, sb2, pooled, Bs, bs_u,
                    tid, wm, wn, gid, tig);
    __syncthreads();

    if (tid < 256)
        g_hbar[bi * HID_ + tid] = pooled[tid] * (1.f / 128.f);
}

// ---------------------------------------------------------------------------
// Dec: out = relu(hbar @ W34 + b34) @ wd2 + bd2
// 256 CTAs x 4 rows. Layer 1: cp.async double-buffered W34 chunks. Layer 2:
// register-prefetched wd2.
// ---------------------------------------------------------------------------
#define DEC_HP 257
#define DEC_SMEM_FLOATS (2 * 32 * HID_ + 2 * 4 * DEC_HP + HID_)
#define DEC_SMEM (DEC_SMEM_FLOATS * 4)

__global__ void __launch_bounds__(256) dec_kernel(const float* __restrict__ wd2,
                                                  const float* __restrict__ bd2,
                                                  float* __restrict__ out) {
    extern __shared__ float dsm[];
    float* Wb   = dsm;                       // 2 * 32*256
    float* hb   = Wb + 2 * 32 * HID_;        // 4*DEC_HP
    float* tt   = hb + 4 * DEC_HP;           // 4*DEC_HP
    float* sb34 = tt + 4 * DEC_HP;           // 256

    const int tid = threadIdx.x;
    const int r0 = blockIdx.x * 4;
    const uint32_t wb_u = smem_u32(Wb);

    for (int idx = tid; idx < 4 * HID_; idx += 256)
        hb[(idx >> 8) * DEC_HP + (idx & 255)] = g_hbar[(r0 + (idx >> 8)) * HID_ + (idx & 255)];
    sb34[tid] = g_b34[tid];
    __syncthreads();

    // ---- layer 1: acc[r] = sum_k hb[r][k] * W34[k][tid] ----
    float a0 = 0.f, a1 = 0.f, a2 = 0.f, a3 = 0.f;
    {
        const float4* src = (const float4*)g_w34;
        #pragma unroll
        for (int i = 0; i < 8; i++)
            CP_ASYNC16(wb_u + (uint32_t)(tid + i * 256) * 16u, src + tid + i * 256);
        CP_COMMIT();
    }
    #pragma unroll 1
    for (int kc = 0; kc < 8; kc++) {
        if (kc < 7) {
            const float4* src = (const float4*)(g_w34 + (kc + 1) * 32 * HID_);
            uint32_t boff = (uint32_t)(((kc + 1) & 1) * 32 * HID_) * 4u;
            #pragma unroll
            for (int i = 0; i < 8; i++)
                CP_ASYNC16(wb_u + boff + (uint32_t)(tid + i * 256) * 16u, src + tid + i * 256);
            CP_COMMIT();
            CP_WAIT(1);
        } else {
            CP_WAIT(0);
        }
        __syncthreads();
        const float* Wc = Wb + (kc & 1) * 32 * HID_;
        const int kb = kc * 32;
        #pragma unroll
        for (int k = 0; k < 32; k++) {
            float wv = Wc[k * HID_ + tid];
            a0 = fmaf(hb[0 * DEC_HP + kb + k], wv, a0);
            a1 = fmaf(hb[1 * DEC_HP + kb + k], wv, a1);
            a2 = fmaf(hb[2 * DEC_HP + kb + k], wv, a2);
            a3 = fmaf(hb[3 * DEC_HP + kb + k], wv, a3);
        }
        __syncthreads();
    }
    tt[0 * DEC_HP + tid] = fmaxf(a0 + sb34[tid], 0.f);
    tt[1 * DEC_HP + tid] = fmaxf(a1 + sb34[tid], 0.f);
    tt[2 * DEC_HP + tid] = fmaxf(a2 + sb34[tid], 0.f);
    tt[3 * DEC_HP + tid] = fmaxf(a3 + sb34[tid], 0.f);
    __syncthreads();

    // ---- layer 2: out[r0+rr][c] = sum_k tt[rr][k] * wd2[k][c] ----
    const int c = tid & 63, rr = tid >> 6;
    const float* trow = tt + rr * DEC_HP;
    float o = 0.f;
    float wv[8];
    #pragma unroll
    for (int q = 0; q < 8; q++) wv[q] = wd2[q * INP_ + c];
    #pragma unroll 1
    for (int k0 = 0; k0 < HID_; k0 += 8) {
        float wnx[8];
        if (k0 + 8 < HID_) {
            #pragma unroll
            for (int q = 0; q < 8; q++) wnx[q] = wd2[(k0 + 8 + q) * INP_ + c];
        }
        #pragma unroll
        for (int q = 0; q < 8; q++) o = fmaf(trow[k0 + q], wv[q], o);
        #pragma unroll
        for (int q = 0; q < 8; q++) wv[q] = wnx[q];
    }
    out[(r0 + rr) * INP_ + c] = o + bd2[c];
}

// ---------------------------------------------------------------------------
extern "C" void kernel_launch(void* const* d_in, const int* in_sizes, int n_in,
                              void* d_out, int out_size) {
    const float* x0    = (const float*)d_in[0];
    const float* x1    = (const float*)d_in[1];
    const float* x2    = (const float*)d_in[2];
    const float* w_enc = (const float*)d_in[3];
    const float* b_enc = (const float*)d_in[4];
    const float* w1    = (const float*)d_in[5];
    const float* b1    = (const float*)d_in[6];
    const float* w2    = (const float*)d_in[7];
    const float* b2    = (const float*)d_in[8];
    const float* w3    = (const float*)d_in[9];
    const float* b3    = (const float*)d_in[10];
    const float* wd1   = (const float*)d_in[11];
    const float* bd1   = (const float*)d_in[12];
    const float* wd2   = (const float*)d_in[13];
    const float* bd2   = (const float*)d_in[14];
    float* out = (float*)d_out;

    cudaFuncSetAttribute(main_kernel,
                         cudaFuncAttributeMaxDynamicSharedMemorySize, SMEM_DYN);
    cudaFuncSetAttribute(dec_kernel,
                         cudaFuncAttributeMaxDynamicSharedMemorySize, DEC_SMEM);

    prep_kernel<<<256, 256>>>(w1, w2);
    prep_w34_kernel<<<257, 256>>>(w3, b3, wd1, bd1);
    enc_kernel<<<ROWS_ / 8, 256>>>(x0, x1, x2, w_enc);
    main_kernel<<<ROWS_, 512, SMEM_DYN>>>(b_enc, b1, b2);
    dec_kernel<<<ROWS_ / 4, 256, DEC_SMEM>>>(wd2, bd2, out);
}

// round 9
// speedup vs baseline: 4.9518x; 1.0234x over previous
#include <cuda_runtime.h>
#include <cstdint>

#define B_   8
#define OBJ_ 128
#define INP_ 64
#define HID_ 256
#define D_   192
#define ROWS_ (B_*OBJ_)   // 1024

// ---------------- device scratch (allocation-free) ----------------
__device__ __align__(256) float g_ea[ROWS_ * HID_];
__device__ __align__(256) float g_eb[ROWS_ * HID_];
__device__ __align__(256) float g_hbar[ROWS_ * HID_];     // mean_j relu(H2)
__device__ __align__(256) float g_w12[2 * HID_ * HID_];   // tf32, frag-scrambled W1,W2
__device__ __align__(256) float g_w34[HID_ * HID_];       // w3 @ wd1 (fp32)
__device__ __align__(256) float g_b34[HID_];              // b3 @ wd1 + bd1

// ---------------- helpers ----------------
__device__ __forceinline__ uint32_t smem_u32(const void* p) {
    uint32_t a;
    asm("{ .reg .u64 t; cvta.to.shared.u64 t, %1; cvt.u32.u64 %0, t; }" : "=r"(a) : "l"(p));
    return a;
}
__device__ __forceinline__ uint32_t tf32_rna(float f) {
    uint32_t r;
    asm("cvt.rna.tf32.f32 %0, %1;" : "=r"(r) : "f"(f));
    return r;
}
__device__ __forceinline__ void mma_tf32(float d[4], const float4 a, uint32_t b0, uint32_t b1) {
    asm volatile(
        "mma.sync.aligned.m16n8k8.row.col.f32.tf32.tf32.f32 "
        "{%0,%1,%2,%3}, {%4,%5,%6,%7}, {%8,%9}, {%0,%1,%2,%3};"
        : "+f"(d[0]), "+f"(d[1]), "+f"(d[2]), "+f"(d[3])
        : "r"(__float_as_uint(a.x)), "r"(__float_as_uint(a.y)),
          "r"(__float_as_uint(a.z)), "r"(__float_as_uint(a.w)),
          "r"(b0), "r"(b1));
}
#define CP_ASYNC16(dst, src) \
    asm volatile("cp.async.cg.shared.global [%0], [%1], 16;" :: "r"(dst), "l"(src))
#define CP_COMMIT() asm volatile("cp.async.commit_group;" ::: "memory")
#define CP_WAIT(n)  asm volatile("cp.async.wait_group %0;" :: "n"(n) : "memory")

// A scrambled layout: 16(row)x8(k) tiles of 128 floats; tile id = (k/8)*8 + (r/16)
// within tile: pos = lane*4 + slot, lane=(r16&7)*4+(kk&3), slot=(kk>>2)*2+(r16>>3)
__device__ __forceinline__ int scr_pos(int r16, int kk) {
    return (((r16 & 7) << 2) + (kk & 3)) * 4 + ((kk >> 2) << 1) + (r16 >> 3);
}
__device__ __forceinline__ int scr_off(int r, int c) {
    return (((c >> 3) << 3) + (r >> 4)) * 128 + scr_pos(r & 15, c & 7);
}

#define BUFV (32 * HID_)    // one 32-k-row scrambled weight chunk (floats)

// ---------------------------------------------------------------------------
// Prep A: round W1,W2 to tf32 AND scramble to fragment-native 8x8-tile layout.
// Chunk kc: offset = kc*8192 + (tk4*32 + tn)*64 + pos, pos=(nn*4+(kk&3))*2+(kk>>2)
// ---------------------------------------------------------------------------
__global__ void prep_kernel(const float* __restrict__ w1, const float* __restrict__ w2) {
    int idx = blockIdx.x * 256 + threadIdx.x;          // k*256+n, 65536 total
    int k = idx >> 8, n = idx & 255;
    int kc = k >> 5, tk4 = (k >> 3) & 3, tn = n >> 3;
    int kk = k & 7, nn = n & 7;
    int pos = ((nn << 2) + (kk & 3)) * 2 + (kk >> 2);
    int off = kc * 8192 + (tk4 * 32 + tn) * 64 + pos;
    g_w12[off]               = __uint_as_float(tf32_rna(w1[idx]));
    g_w12[HID_ * HID_ + off] = __uint_as_float(tf32_rna(w2[idx]));
}

// ---------------------------------------------------------------------------
// Prep B: W34 = w3 @ wd1 ; b34 = b3 @ wd1 + bd1
// ---------------------------------------------------------------------------
__global__ void __launch_bounds__(256) prep_w34_kernel(const float* __restrict__ w3,
                                                       const float* __restrict__ b3,
                                                       const float* __restrict__ wd1,
                                                       const float* __restrict__ bd1) {
    __shared__ float row[HID_];
    const int m = blockIdx.x;
    const int tid = threadIdx.x;
    row[tid] = (m < 256) ? w3[m * HID_ + tid] : b3[tid];
    __syncthreads();
    float acc = 0.f;
    float wv[8];
    #pragma unroll
    for (int q = 0; q < 8; q++) wv[q] = wd1[q * HID_ + tid];
    #pragma unroll 1
    for (int k0 = 0; k0 < HID_; k0 += 8) {
        float wnx[8];
        if (k0 + 8 < HID_) {
            #pragma unroll
            for (int q = 0; q < 8; q++) wnx[q] = wd1[(k0 + 8 + q) * HID_ + tid];
        }
        #pragma unroll
        for (int q = 0; q < 8; q++) acc = fmaf(row[k0 + q], wv[q], acc);
        #pragma unroll
        for (int q = 0; q < 8; q++) wv[q] = wnx[q];
    }
    if (m < 256) g_w34[m * HID_ + tid] = acc;
    else         g_b34[tid] = acc + bd1[tid];
}

// ---------------------------------------------------------------------------
// Encoder: 8 rows per CTA
// ---------------------------------------------------------------------------
__global__ void __launch_bounds__(256) enc_kernel(const float* __restrict__ x0,
                                                  const float* __restrict__ x1,
                                                  const float* __restrict__ x2,
                                                  const float* __restrict__ w_enc) {
    __shared__ float xs[8][D_];
    const int tid = threadIdx.x;
    const int r0 = blockIdx.x * 8;
    for (int idx = tid; idx < 8 * D_; idx += 256) {
        int r = idx / D_, d = idx % D_;
        int part = d >> 6, dd = d & 63;
        const float* src = (part == 0) ? x0 : ((part == 1) ? x1 : x2);
        xs[r][d] = src[(r0 + r) * INP_ + dd];
    }
    __syncthreads();
    float sa[8], sb[8];
    #pragma unroll
    for (int r = 0; r < 8; r++) { sa[r] = 0.f; sb[r] = 0.f; }
    #pragma unroll 1
    for (int d0 = 0; d0 < D_; d0 += 4) {
        float wa[4], wb[4];
        #pragma unroll
        for (int q = 0; q < 4; q++) {
            wa[q] = w_enc[(d0 + q) * HID_ + tid];
            wb[q] = w_enc[(D_ + d0 + q) * HID_ + tid];
        }
        #pragma unroll
        for (int q = 0; q < 4; q++)
            #pragma unroll
            for (int r = 0; r < 8; r++) {
                sa[r] = fmaf(xs[r][d0 + q], wa[q], sa[r]);
                sb[r] = fmaf(xs[r][d0 + q], wb[q], sb[r]);
            }
    }
    #pragma unroll
    for (int r = 0; r < 8; r++) {
        g_ea[(r0 + r) * HID_ + tid] = sa[r];
        g_eb[(r0 + r) * HID_ + tid] = sb[r];
    }
}

// ---------------------------------------------------------------------------
// One 128x256 @ 256x256 tf32-HMMA layer, 16 warps as 2M x 8N, warp tile 64x32.
// Fragment-native layouts: A-frag = 1 LDS.128, B-frag = 1 LDS.64.
// ---------------------------------------------------------------------------
template <bool POOL>
__device__ __forceinline__ void run_layer(float* __restrict__ As,
                                          const float* __restrict__ gW,
                                          const float* __restrict__ bias,
                                          float* __restrict__ pooled,
                                          float* __restrict__ Bs, uint32_t bs_u,
                                          int tid, int wm, int wn, int gid, int tig,
                                          int lane) {
    float d[4][4][4];
    #pragma unroll
    for (int mf = 0; mf < 4; mf++)
        #pragma unroll
        for (int nf = 0; nf < 4; nf++)
            #pragma unroll
            for (int q = 0; q < 4; q++) d[mf][nf][q] = 0.f;

    const float4* As4 = (const float4*)As;

    // stage chunk 0 (linear 32KB copy)
    {
        const float4* src = (const float4*)gW;
        #pragma unroll
        for (int i = 0; i < 4; i++)
            CP_ASYNC16(bs_u + (uint32_t)(tid + i * 512) * 16u, src + tid + i * 512);
        CP_COMMIT();
    }

    #pragma unroll 1
    for (int kc = 0; kc < 8; kc++) {
        if (kc < 7) {
            const float4* src = (const float4*)(gW + (kc + 1) * BUFV);
            uint32_t boff = (uint32_t)(((kc + 1) & 1) * BUFV) * 4u;
            #pragma unroll
            for (int i = 0; i < 4; i++)
                CP_ASYNC16(bs_u + boff + (uint32_t)(tid + i * 512) * 16u, src + tid + i * 512);
            CP_COMMIT();
            CP_WAIT(1);
        } else {
            CP_WAIT(0);
        }
        __syncthreads();

        const float2* Bb2 = (const float2*)(Bs + (kc & 1) * BUFV);
        #pragma unroll
        for (int ks = 0; ks < 4; ks++) {
            const int ct = kc * 4 + ks;                 // k-tile id (k/8)
            float4 a[4];
            #pragma unroll
            for (int mf = 0; mf < 4; mf++)
                a[mf] = As4[(ct * 8 + wm * 4 + mf) * 32 + lane];   // tile=128 floats=32 f4
            #pragma unroll
            for (int nf = 0; nf < 4; nf++) {
                float2 bv = Bb2[(ks * 32 + wn * 4 + nf) * 32 + lane];
                uint32_t b0 = __float_as_uint(bv.x);
                uint32_t b1 = __float_as_uint(bv.y);
                #pragma unroll
                for (int mf = 0; mf < 4; mf++)
                    mma_tf32(d[mf][nf], a[mf], b0, b1);
            }
        }
        __syncthreads();
    }
    // all reads of As done (barrier above) -> in-place epilogue safe

    if (!POOL) {
        #pragma unroll
        for (int mf = 0; mf < 4; mf++) {
            const int r0 = wm * 64 + mf * 16 + gid;
            #pragma unroll
            for (int nf = 0; nf < 4; nf++) {
                const int c = wn * 32 + nf * 8 + 2 * tig;
                As[scr_off(r0, c)]         = __uint_as_float(tf32_rna(fmaxf(d[mf][nf][0] + bias[c], 0.f)));
                As[scr_off(r0, c + 1)]     = __uint_as_float(tf32_rna(fmaxf(d[mf][nf][1] + bias[c + 1], 0.f)));
                As[scr_off(r0 + 8, c)]     = __uint_as_float(tf32_rna(fmaxf(d[mf][nf][2] + bias[c], 0.f)));
                As[scr_off(r0 + 8, c + 1)] = __uint_as_float(tf32_rna(fmaxf(d[mf][nf][3] + bias[c + 1], 0.f)));
            }
        }
    } else {
        #pragma unroll
        for (int nf = 0; nf < 4; nf++) {
            const int c0 = wn * 32 + nf * 8 + 2 * tig;
            const float bc0 = bias[c0], bc1 = bias[c0 + 1];
            float s0 = 0.f, s1 = 0.f;
            #pragma unroll
            for (int mf = 0; mf < 4; mf++) {
                s0 += fmaxf(d[mf][nf][0] + bc0, 0.f) + fmaxf(d[mf][nf][2] + bc0, 0.f);
                s1 += fmaxf(d[mf][nf][1] + bc1, 0.f) + fmaxf(d[mf][nf][3] + bc1, 0.f);
            }
            #pragma unroll
            for (int off = 4; off < 32; off <<= 1) {
                s0 += __shfl_xor_sync(0xFFFFFFFFu, s0, off);
                s1 += __shfl_xor_sync(0xFFFFFFFFu, s1, off);
            }
            if (gid == 0) {
                atomicAdd(&pooled[c0], s0);
                atomicAdd(&pooled[c0 + 1], s1);
            }
        }
    }
}

// ---------------------------------------------------------------------------
// Main: one CTA per (b,i); single pass over 128 j-rows; 512 threads.
// ---------------------------------------------------------------------------
#define SMEM_FLOATS (128 * HID_ + 2 * BUFV + 5 * HID_)
#define SMEM_DYN    (SMEM_FLOATS * 4)

__global__ void __launch_bounds__(512, 1)
main_kernel(const float* __restrict__ b_enc,
            const float* __restrict__ b1, const float* __restrict__ b2) {
    extern __shared__ float sm[];
    float* A0     = sm;                     // 128*256 scrambled
    float* Bs     = A0 + 128 * HID_;        // 2*BUFV
    float* pooled = Bs + 2 * BUFV;          // 256
    float* ea_s   = pooled + HID_;
    float* sbenc  = ea_s + HID_;
    float* sb1    = sbenc + HID_;
    float* sb2    = sb1 + HID_;

    const int tid  = threadIdx.x;
    const int lane = tid & 31;
    const int w    = tid >> 5;              // 0..15
    const int wm   = w >> 3;                // 0..1 (64-row group)
    const int wn   = w & 7;                 // 0..7 (32-col group)
    const int gid  = lane >> 2;
    const int tig  = lane & 3;
    const int bi   = blockIdx.x;
    const int b    = bi >> 7;
    const uint32_t bs_u = smem_u32(Bs);

    if (tid < 256) {
        ea_s[tid]   = g_ea[bi * HID_ + tid];
        sbenc[tid]  = b_enc[tid];
        sb1[tid]    = b1[tid];
        sb2[tid]    = b2[tid];
        pooled[tid] = 0.f;
    }
    __syncthreads();

    // ---- build A0 = tf32(relu(ea_i + eb_j + b_enc)), scrambled ----
    const float4* ebr = (const float4*)(g_eb + (b * OBJ_) * HID_);
    #pragma unroll
    for (int i = 0; i < 16; i++) {
        int idx = tid + i * 512;           // 8192 float4
        int r = idx >> 6, c4 = idx & 63;
        float4 e = ebr[idx];
        int c = c4 * 4;
        int tb = (((c >> 3) << 3) + (r >> 4)) * 128;    // tile = 128 floats
        int r16 = r & 15, kk0 = c & 7;                  // kk0 in {0,4}
        int base = tb + ((r16 & 7) << 4) + ((kk0 >> 2) << 1) + (r16 >> 3);
        A0[base + 0]  = __uint_as_float(tf32_rna(fmaxf(ea_s[c + 0] + e.x + sbenc[c + 0], 0.f)));
        A0[base + 4]  = __uint_as_float(tf32_rna(fmaxf(ea_s[c + 1] + e.y + sbenc[c + 1], 0.f)));
        A0[base + 8]  = __uint_as_float(tf32_rna(fmaxf(ea_s[c + 2] + e.z + sbenc[c + 2], 0.f)));
        A0[base + 12] = __uint_as_float(tf32_rna(fmaxf(ea_s[c + 3] + e.w + sbenc[c + 3], 0.f)));
    }
    __syncthreads();

    run_layer<false>(A0, g_w12, sb1, pooled, Bs, bs_u, tid, wm, wn, gid, tig, lane);
    __syncthreads();
    run_layer<true>(A0, g_w12 + HID_ * HID_, sb2, pooled, Bs, bs_u,
                    tid, wm, wn, gid, tig, lane);
    __syncthreads();

    if (tid < 256)
        g_hbar[bi * HID_ + tid] = pooled[tid] * (1.f / 128.f);
}

// ---------------------------------------------------------------------------
// Dec: out = relu(hbar @ W34 + b34) @ wd2 + bd2
// ---------------------------------------------------------------------------
#define DEC_HP 257
#define DEC_SMEM_FLOATS (2 * 32 * HID_ + 2 * 4 * DEC_HP + HID_)
#define DEC_SMEM (DEC_SMEM_FLOATS * 4)

__global__ void __launch_bounds__(256) dec_kernel(const float* __restrict__ wd2,
                                                  const float* __restrict__ bd2,
                                                  float* __restrict__ out) {
    extern __shared__ float dsm[];
    float* Wb   = dsm;                       // 2 * 32*256
    float* hb   = Wb + 2 * 32 * HID_;        // 4*DEC_HP
    float* tt   = hb + 4 * DEC_HP;           // 4*DEC_HP
    float* sb34 = tt + 4 * DEC_HP;           // 256

    const int tid = threadIdx.x;
    const int r0 = blockIdx.x * 4;
    const uint32_t wb_u = smem_u32(Wb);

    for (int idx = tid; idx < 4 * HID_; idx += 256)
        hb[(idx >> 8) * DEC_HP + (idx & 255)] = g_hbar[(r0 + (idx >> 8)) * HID_ + (idx & 255)];
    sb34[tid] = g_b34[tid];
    __syncthreads();

    float a0 = 0.f, a1 = 0.f, a2 = 0.f, a3 = 0.f;
    {
        const float4* src = (const float4*)g_w34;
        #pragma unroll
        for (int i = 0; i < 8; i++)
            CP_ASYNC16(wb_u + (uint32_t)(tid + i * 256) * 16u, src + tid + i * 256);
        CP_COMMIT();
    }
    #pragma unroll 1
    for (int kc = 0; kc < 8; kc++) {
        if (kc < 7) {
            const float4* src = (const float4*)(g_w34 + (kc + 1) * 32 * HID_);
            uint32_t boff = (uint32_t)(((kc + 1) & 1) * 32 * HID_) * 4u;
            #pragma unroll
            for (int i = 0; i < 8; i++)
                CP_ASYNC16(wb_u + boff + (uint32_t)(tid + i * 256) * 16u, src + tid + i * 256);
            CP_COMMIT();
            CP_WAIT(1);
        } else {
            CP_WAIT(0);
        }
        __syncthreads();
        const float* Wc = Wb + (kc & 1) * 32 * HID_;
        const int kb = kc * 32;
        #pragma unroll
        for (int k = 0; k < 32; k++) {
            float wv = Wc[k * HID_ + tid];
            a0 = fmaf(hb[0 * DEC_HP + kb + k], wv, a0);
            a1 = fmaf(hb[1 * DEC_HP + kb + k], wv, a1);
            a2 = fmaf(hb[2 * DEC_HP + kb + k], wv, a2);
            a3 = fmaf(hb[3 * DEC_HP + kb + k], wv, a3);
        }
        __syncthreads();
    }
    tt[0 * DEC_HP + tid] = fmaxf(a0 + sb34[tid], 0.f);
    tt[1 * DEC_HP + tid] = fmaxf(a1 + sb34[tid], 0.f);
    tt[2 * DEC_HP + tid] = fmaxf(a2 + sb34[tid], 0.f);
    tt[3 * DEC_HP + tid] = fmaxf(a3 + sb34[tid], 0.f);
    __syncthreads();

    const int c = tid & 63, rr = tid >> 6;
    const float* trow = tt + rr * DEC_HP;
    float o = 0.f;
    float wv[8];
    #pragma unroll
    for (int q = 0; q < 8; q++) wv[q] = wd2[q * INP_ + c];
    #pragma unroll 1
    for (int k0 = 0; k0 < HID_; k0 += 8) {
        float wnx[8];
        if (k0 + 8 < HID_) {
            #pragma unroll
            for (int q = 0; q < 8; q++) wnx[q] = wd2[(k0 + 8 + q) * INP_ + c];
        }
        #pragma unroll
        for (int q = 0; q < 8; q++) o = fmaf(trow[k0 + q], wv[q], o);
        #pragma unroll
        for (int q = 0; q < 8; q++) wv[q] = wnx[q];
    }
    out[(r0 + rr) * INP_ + c] = o + bd2[c];
}

// ---------------------------------------------------------------------------
extern "C" void kernel_launch(void* const* d_in, const int* in_sizes, int n_in,
                              void* d_out, int out_size) {
    const float* x0    = (const float*)d_in[0];
    const float* x1    = (const float*)d_in[1];
    const float* x2    = (const float*)d_in[2];
    const float* w_enc = (const float*)d_in[3];
    const float* b_enc = (const float*)d_in[4];
    const float* w1    = (const float*)d_in[5];
    const float* b1    = (const float*)d_in[6];
    const float* w2    = (const float*)d_in[7];
    const float* b2    = (const float*)d_in[8];
    const float* w3    = (const float*)d_in[9];
    const float* b3    = (const float*)d_in[10];
    const float* wd1   = (const float*)d_in[11];
    const float* bd1   = (const float*)d_in[12];
    const float* wd2   = (const float*)d_in[13];
    const float* bd2   = (const float*)d_in[14];
    float* out = (float*)d_out;

    cudaFuncSetAttribute(main_kernel,
                         cudaFuncAttributeMaxDynamicSharedMemorySize, SMEM_DYN);
    cudaFuncSetAttribute(dec_kernel,
                         cudaFuncAttributeMaxDynamicSharedMemorySize, DEC_SMEM);

    prep_kernel<<<256, 256>>>(w1, w2);
    prep_w34_kernel<<<257, 256>>>(w3, b3, wd1, bd1);
    enc_kernel<<<ROWS_ / 8, 256>>>(x0, x1, x2, w_enc);
    main_kernel<<<ROWS_, 512, SMEM_DYN>>>(b_enc, b1, b2);
    dec_kernel<<<ROWS_ / 4, 256, DEC_SMEM>>>(wd2, bd2, out);
}